// round 1
// baseline (speedup 1.0000x reference)
#include <cuda_runtime.h>
#include <cuda_bf16.h>
#include <cstdint>

#define BN    32
#define CH    256
#define HH    56
#define WW    56
#define HW    (HH*WW)            // 3136
#define TOTAL (BN*CH*HW)         // 25690112
#define WELEMS (CH*CH*9)         // 589824
#define KPACK 128                // u32 (bf16 pairs) per pixel

// -------- device scratch (no allocations allowed in kernel_launch) --------
__device__ float        g_pre[TOTAL];                 // conv + residual (pre-BN), ~103MB
__device__ unsigned int g_bx[BN*HW*KPACK];            // packed sign(x) bf16 pairs, ~49MB
__device__ unsigned int g_w2[9*KPACK*CH];             // packed sign(w) bf16 pairs [tap][k2][cout]
__device__ float        g_meanval;
__device__ float        g_scale[CH];
__device__ float        g_bias[CH];

__device__ __forceinline__ unsigned sgn_bf16(float v) {
    // bf16(+1)=0x3F80, bf16(-1)=0xBF80, sign(0)=0
    return v > 0.f ? 0x3F80u : (v < 0.f ? 0xBF80u : 0u);
}

// ---------------- P0: mean(|clip(w,-1,1)|), single block, deterministic ----
__global__ void k_meanval(const float* __restrict__ w) {
    __shared__ float red[1024];
    float s = 0.f;
    for (int i = threadIdx.x; i < WELEMS; i += 1024) {
        float v = fabsf(w[i]);
        s += (v < 1.f) ? v : 1.f;
    }
    red[threadIdx.x] = s;
    __syncthreads();
    for (int o = 512; o > 0; o >>= 1) {
        if (threadIdx.x < o) red[threadIdx.x] += red[threadIdx.x + o];
        __syncthreads();
    }
    if (threadIdx.x == 0) g_meanval = red[0] / (float)WELEMS;
}

// ---------------- P1: pack weight signs as bf16 pairs [tap][k2][cout] ------
__global__ void k_packw(const float* __restrict__ w) {
    int idx = blockIdx.x * 256 + threadIdx.x;
    if (idx >= 9 * KPACK * CH) return;
    int tap = idx / (KPACK * CH);
    int rem = idx % (KPACK * CH);
    int k2 = rem / CH;
    int n  = rem % CH;           // c_out
    int kh = tap / 3, kw = tap % 3;
    int base = ((n * CH + 2 * k2) * 3 + kh) * 3 + kw;   // w[co][ci][kh][kw]
    unsigned lo = sgn_bf16(w[base]);
    unsigned hi = sgn_bf16(w[base + 9]);                // ci+1 (stride 9)
    g_w2[idx] = lo | (hi << 16);
}

// ---------------- P2: sign(x) -> channel-last packed bf16 pairs ------------
// one block per (b,h); smem transpose for coalesced read and write
__global__ void k_packx(const float* __restrict__ x) {
    __shared__ unsigned short tile[WW * 258];   // stride 258 avoids bank conflicts, keeps u32 alignment
    int b = blockIdx.x / HH, h = blockIdx.x % HH;
    for (int i = threadIdx.x; i < CH * WW; i += 256) {
        int c = i / WW, w = i - c * WW;
        float v = x[((b * CH + c) * HH + h) * WW + w];
        tile[w * 258 + c] = (unsigned short)sgn_bf16(v);
    }
    __syncthreads();
    unsigned* t32 = (unsigned*)tile;
    for (int j = threadIdx.x; j < WW * KPACK; j += 256) {
        int w = j >> 7, k = j & 127;
        g_bx[((b * HH + h) * WW + w) * KPACK + k] = t32[w * 129 + k];
    }
}

// ---------------- conv: implicit GEMM via mma.sync m16n8k16 bf16 -----------
__device__ __forceinline__ void mma16816(float* c, const unsigned* a, const unsigned* b) {
    asm volatile(
        "mma.sync.aligned.m16n8k16.row.col.f32.bf16.bf16.f32 "
        "{%0,%1,%2,%3}, {%4,%5,%6,%7}, {%8,%9}, {%0,%1,%2,%3};\n"
        : "+f"(c[0]), "+f"(c[1]), "+f"(c[2]), "+f"(c[3])
        : "r"(a[0]), "r"(a[1]), "r"(a[2]), "r"(a[3]), "r"(b[0]), "r"(b[1]));
}

// tile: 128 pixels (16h x 8w) x 256 c_out per block; 8 warps, each 64px x 64co
__global__ __launch_bounds__(256, 1) void k_conv(const float* __restrict__ x) {
    __shared__ unsigned Asm[180 * 8];   // 18x10 pixel neighborhood x 8 u32 (16 ch)
    __shared__ unsigned Bsm[8 * 256];   // 16 k x 256 n (k-pair packed)

    const int tid  = threadIdx.x;
    const int warp = tid >> 5, lane = tid & 31;
    const int grp  = lane >> 2, tig = lane & 3;
    const int wm   = warp >> 2, wn = warp & 3;
    const int tw = blockIdx.x, th = blockIdx.y, b = blockIdx.z;
    const int h0 = th * 16, w0 = tw * 8;

    float acc[4][8][4];
#pragma unroll
    for (int i = 0; i < 4; i++)
#pragma unroll
        for (int j = 0; j < 8; j++)
#pragma unroll
            for (int e = 0; e < 4; e++) acc[i][j][e] = 0.f;

    for (int kc = 0; kc < 16; kc++) {
        __syncthreads();
        // stage activation neighborhood for this 16-channel chunk (zero pad)
        for (int i = tid; i < 1440; i += 256) {
            int nbp = i >> 3, kk = i & 7;
            int nh = h0 - 1 + nbp / 10;
            int nw = w0 - 1 + nbp % 10;
            unsigned v = 0u;
            if (nh >= 0 && nh < HH && nw >= 0 && nw < WW)
                v = g_bx[(unsigned)((b * HH + nh) * WW + nw) * KPACK + kc * 8 + kk];
            Asm[i] = v;
        }
        for (int tap = 0; tap < 9; tap++) {
            __syncthreads();      // Asm ready / previous Bsm consumers done
            for (int i = tid; i < 2048; i += 256)
                Bsm[i] = g_w2[(tap * KPACK + kc * 8) * CH + i];
            __syncthreads();
            const int dh = tap / 3, dw = tap % 3;

            unsigned afr[4][4];
#pragma unroll
            for (int fm = 0; fm < 4; fm++) {
                int p0 = wm * 64 + fm * 16 + grp;
                int p1 = p0 + 8;
                int nb0 = (((p0 >> 3) + dh) * 10 + (p0 & 7) + dw) * 8;
                int nb1 = (((p1 >> 3) + dh) * 10 + (p1 & 7) + dw) * 8;
                afr[fm][0] = Asm[nb0 + tig];
                afr[fm][1] = Asm[nb1 + tig];
                afr[fm][2] = Asm[nb0 + tig + 4];
                afr[fm][3] = Asm[nb1 + tig + 4];
            }
            unsigned bfr[8][2];
#pragma unroll
            for (int fn = 0; fn < 8; fn++) {
                int n = wn * 64 + fn * 8 + grp;
                bfr[fn][0] = Bsm[tig * 256 + n];
                bfr[fn][1] = Bsm[(tig + 4) * 256 + n];
            }
#pragma unroll
            for (int fm = 0; fm < 4; fm++)
#pragma unroll
                for (int fn = 0; fn < 8; fn++)
                    mma16816(acc[fm][fn], afr[fm], bfr[fn]);
        }
    }

    // epilogue: scale by mean(|w|), add residual, write pre-BN
    const float mv = g_meanval;
#pragma unroll
    for (int fm = 0; fm < 4; fm++) {
#pragma unroll
        for (int e2 = 0; e2 < 2; e2++) {
            int p = wm * 64 + fm * 16 + grp + e2 * 8;
            int h = h0 + (p >> 3), w = w0 + (p & 7);
            if (h < HH) {
#pragma unroll
                for (int fn = 0; fn < 8; fn++) {
#pragma unroll
                    for (int e1 = 0; e1 < 2; e1++) {
                        int co = wn * 64 + fn * 8 + tig * 2 + e1;
                        int idx = ((b * CH + co) * HH + h) * WW + w;
                        g_pre[idx] = mv * acc[fm][fn][e2 * 2 + e1] + x[idx];
                    }
                }
            }
        }
    }
}

// ---------------- R: per-channel BN stats (deterministic tree reduce) ------
__global__ void k_stats(const float* __restrict__ gamma, const float* __restrict__ beta) {
    int c = blockIdx.x;
    __shared__ float rs[256], rq[256];
    float s = 0.f, q = 0.f;
    for (int i = threadIdx.x; i < BN * HW; i += 256) {
        int b = i / HW, sp = i - b * HW;
        float v = g_pre[(b * CH + c) * HW + sp];
        s += v;
        q += v * v;
    }
    rs[threadIdx.x] = s;
    rq[threadIdx.x] = q;
    __syncthreads();
    for (int o = 128; o > 0; o >>= 1) {
        if (threadIdx.x < o) {
            rs[threadIdx.x] += rs[threadIdx.x + o];
            rq[threadIdx.x] += rq[threadIdx.x + o];
        }
        __syncthreads();
    }
    if (threadIdx.x == 0) {
        const float inv = 1.f / (float)(BN * HW);
        float mean = rs[0] * inv;
        float var  = rq[0] * inv - mean * mean;
        float sc = gamma[c] * rsqrtf(var + 1e-5f);
        g_scale[c] = sc;
        g_bias[c]  = beta[c] - mean * sc;
    }
}

// ---------------- E: apply BN affine + ReLU, vectorized --------------------
__global__ void k_finish(float4* __restrict__ out) {
    int i = blockIdx.x * 256 + threadIdx.x;   // TOTAL/4 = 6422528 exactly covered
    int c = (i / (HW / 4)) % CH;
    float sc = g_scale[c], bi = g_bias[c];
    float4 v = ((const float4*)g_pre)[i];
    float4 r;
    r.x = fmaxf(v.x * sc + bi, 0.f);
    r.y = fmaxf(v.y * sc + bi, 0.f);
    r.z = fmaxf(v.z * sc + bi, 0.f);
    r.w = fmaxf(v.w * sc + bi, 0.f);
    out[i] = r;
}

// ---------------- launch ---------------------------------------------------
extern "C" void kernel_launch(void* const* d_in, const int* in_sizes, int n_in,
                              void* d_out, int out_size) {
    const float* x     = (const float*)d_in[0];
    const float* w     = (const float*)d_in[1];
    const float* gamma = (const float*)d_in[2];
    const float* beta  = (const float*)d_in[3];

    k_meanval<<<1, 1024>>>(w);
    k_packw<<<(9 * KPACK * CH + 255) / 256, 256>>>(w);
    k_packx<<<BN * HH, 256>>>(x);
    k_conv<<<dim3(7, 4, BN), 256>>>(x);
    k_stats<<<CH, 256>>>(gamma, beta);
    k_finish<<<TOTAL / 4 / 256, 256>>>((float4*)d_out);
}